// round 1
// baseline (speedup 1.0000x reference)
#include <cuda_runtime.h>
#include <cstdint>

// Problem constants
#define K_CODES 8192
#define D_DIM   256
#define N_Q     16384
#define HW      1024   // 32*32
#define QT      128    // queries per block (main kernel)
#define CT      64     // codes per chunk

// Scratch (device globals: allocation-free rule)
__device__ float g_cbT[(size_t)D_DIM * K_CODES];  // [d][k] transposed codebook
__device__ float g_c2[K_CODES];
__device__ float g_z2[N_Q];

// ---------- helpers: packed f32x2 ----------
__device__ __forceinline__ unsigned long long dup2(float x) {
    unsigned long long r;
    asm("mov.b64 %0, {%1, %1};" : "=l"(r) : "r"(__float_as_uint(x)));
    return r;
}
__device__ __forceinline__ void fma2(unsigned long long& d, unsigned long long a,
                                     unsigned long long b) {
    asm("fma.rn.f32x2 %0, %1, %2, %0;" : "+l"(d) : "l"(a), "l"(b));
}
__device__ __forceinline__ float2 unpack2(unsigned long long v) {
    float2 r;
    asm("mov.b64 {%0, %1}, %2;" : "=f"(r.x), "=f"(r.y) : "l"(v));
    return r;
}

// ---------- kernel 1: codebook transpose cb[k][d] -> g_cbT[d][k] ----------
__global__ void k_transpose(const float* __restrict__ cb) {
    __shared__ float tile[32][33];
    int k0 = blockIdx.x * 32, d0 = blockIdx.y * 32;
    int tx = threadIdx.x, ty = threadIdx.y;  // 32 x 8
#pragma unroll
    for (int j = 0; j < 32; j += 8)
        tile[ty + j][tx] = cb[(size_t)(k0 + ty + j) * D_DIM + d0 + tx];
    __syncthreads();
#pragma unroll
    for (int j = 0; j < 32; j += 8)
        g_cbT[(size_t)(d0 + ty + j) * K_CODES + k0 + tx] = tile[tx][ty + j];
}

// ---------- kernel 2: c2[k] = sum_d fl(cb*cb)  (rounded products, like jnp) ----------
__global__ void k_c2(const float* __restrict__ cb) {
    int w = (blockIdx.x * blockDim.x + threadIdx.x) >> 5;
    int lane = threadIdx.x & 31;
    if (w >= K_CODES) return;
    float s = 0.f;
#pragma unroll
    for (int i = 0; i < 8; i++) {
        float v = cb[(size_t)w * D_DIM + lane + i * 32];
        s = __fadd_rn(s, __fmul_rn(v, v));
    }
#pragma unroll
    for (int o = 16; o; o >>= 1)
        s = __fadd_rn(s, __shfl_xor_sync(0xffffffffu, s, o));
    if (lane == 0) g_c2[w] = s;
}

// ---------- kernel 3: z2[q], sequential-d order guess, rounded products ----------
__global__ void k_z2(const float* __restrict__ z) {
    int q = blockIdx.x * blockDim.x + threadIdx.x;
    int b = q >> 10, hw = q & 1023;
    const float* p = z + (size_t)b * (D_DIM * HW) + hw;
    float s = 0.f;
    for (int d = 0; d < D_DIM; d++) {
        float v = p[(size_t)d * HW];
        s = __fadd_rn(s, __fmul_rn(v, v));
    }
    g_z2[q] = s;
}

// ---------- main kernel: fused GEMM + argmin + gather/scatter ----------
// block = 256 threads, grid = N_Q/QT = 128 blocks (single wave)
// smem: sz[256][128] (z tile, d-major) | sc[256][64] (code chunk, d-major) | sc2[64]
__global__ __launch_bounds__(256, 1) void k_main(const float* __restrict__ z,
                                                 const float* __restrict__ cb,
                                                 float* __restrict__ out,
                                                 int write_idx) {
    extern __shared__ float sm[];
    float* sz  = sm;                        // 256*128 floats
    float* sc  = sm + 256 * 128;            // 256*64 floats
    float* sc2 = sc + 256 * 64;             // 64 floats
    __shared__ int sidx[QT];

    const int t = threadIdx.x;
    const int qbase = blockIdx.x * QT;
    const int b = qbase >> 10, hw0 = qbase & 1023;   // QT=128 divides 1024: one batch per block
    const float* zb = z + (size_t)b * (D_DIM * HW) + hw0;

    // ---- load z tile: 256 d-rows x 128 q, coalesced float4 ----
#pragma unroll
    for (int i = 0; i < 32; i++) {
        int idx = t + i * 256;
        int d = idx >> 5, q4 = idx & 31;
        float4 v = *(const float4*)(zb + (size_t)d * HW + q4 * 4);
        *(float4*)(sz + d * 128 + q4 * 4) = v;
    }

    const int ty = t >> 4;   // 0..15 : owns queries ty*8 .. ty*8+7
    const int tx = t & 15;   // 0..15 : owns codes   tx*4 .. tx*4+3 (per chunk)

    float rz2[8];
#pragma unroll
    for (int i = 0; i < 8; i++) rz2[i] = g_z2[qbase + ty * 8 + i];

    float bestv[8];
    int   bestk[8];
#pragma unroll
    for (int i = 0; i < 8; i++) { bestv[i] = __int_as_float(0x7f800000); bestk[i] = 0; }

    // ---- loop over 128 code chunks of 64 ----
    for (int ch = 0; ch < K_CODES / CT; ch++) {
        const int cbase = ch * CT;
        __syncthreads();
        // load code chunk from transposed codebook (coalesced, conflict-free stores)
#pragma unroll
        for (int i = 0; i < 16; i++) {
            int idx = t + i * 256;
            int d = idx >> 4, c4 = idx & 15;
            float4 v = *(const float4*)(g_cbT + (size_t)d * K_CODES + cbase + c4 * 4);
            *(float4*)(sc + d * 64 + c4 * 4) = v;
        }
        if (t < CT) sc2[t] = g_c2[cbase + t];
        __syncthreads();

        // accumulate dot products: 4 query-pairs x 4 codes, packed f32x2
        unsigned long long acc[4][4];
#pragma unroll
        for (int p = 0; p < 4; p++)
#pragma unroll
            for (int j = 0; j < 4; j++) acc[p][j] = 0ull;

#pragma unroll 4
        for (int d = 0; d < D_DIM; d++) {
            const float* zr = sz + d * 128 + ty * 8;
            ulonglong2 qpa = *(const ulonglong2*)(zr);      // query pairs 0,1
            ulonglong2 qpb = *(const ulonglong2*)(zr + 4);  // query pairs 2,3
            float4 cv = *(const float4*)(sc + d * 64 + tx * 4);
            unsigned long long c0 = dup2(cv.x), c1 = dup2(cv.y),
                               c2d = dup2(cv.z), c3 = dup2(cv.w);
            fma2(acc[0][0], qpa.x, c0); fma2(acc[0][1], qpa.x, c1);
            fma2(acc[0][2], qpa.x, c2d); fma2(acc[0][3], qpa.x, c3);
            fma2(acc[1][0], qpa.y, c0); fma2(acc[1][1], qpa.y, c1);
            fma2(acc[1][2], qpa.y, c2d); fma2(acc[1][3], qpa.y, c3);
            fma2(acc[2][0], qpb.x, c0); fma2(acc[2][1], qpb.x, c1);
            fma2(acc[2][2], qpb.x, c2d); fma2(acc[2][3], qpb.x, c3);
            fma2(acc[3][0], qpb.y, c0); fma2(acc[3][1], qpb.y, c1);
            fma2(acc[3][2], qpb.y, c2d); fma2(acc[3][3], qpb.y, c3);
        }

        // finalize chunk: dist = fl(fl(z2 - fl(2*dot)) + c2), strict < keeps lowest index
#pragma unroll
        for (int jc = 0; jc < 4; jc++) {
            float c2v = sc2[tx * 4 + jc];
            int kg = cbase + tx * 4 + jc;
#pragma unroll
            for (int p = 0; p < 4; p++) {
                float2 dd = unpack2(acc[p][jc]);
                float dist0 = __fadd_rn(__fsub_rn(rz2[2 * p], __fmul_rn(2.0f, dd.x)), c2v);
                float dist1 = __fadd_rn(__fsub_rn(rz2[2 * p + 1], __fmul_rn(2.0f, dd.y)), c2v);
                if (dist0 < bestv[2 * p])     { bestv[2 * p] = dist0;     bestk[2 * p] = kg; }
                if (dist1 < bestv[2 * p + 1]) { bestv[2 * p + 1] = dist1; bestk[2 * p + 1] = kg; }
            }
        }
    }

    // ---- cross-thread argmin reduction (16 tx lanes per query) ----
    __syncthreads();
    float2* red = (float2*)sc;  // reuse chunk smem: 128*16 float2 = 16KB
#pragma unroll
    for (int i = 0; i < 8; i++) {
        int ql = ty * 8 + i;
        red[ql * 16 + tx] = make_float2(bestv[i], __int_as_float(bestk[i]));
    }
    __syncthreads();
    if (t < QT) {
        float bv = __int_as_float(0x7f800000);
        int bk = 0x7fffffff;
#pragma unroll
        for (int j = 0; j < 16; j++) {
            float2 e = red[t * 16 + j];
            int k = __float_as_int(e.y);
            if (e.x < bv || (e.x == bv && k < bk)) { bv = e.x; bk = k; }
        }
        sidx[t] = bk;
        if (write_idx) out[(size_t)N_Q * D_DIM + qbase + t] = (float)bk;
    }
    __syncthreads();

    // ---- write z_q (NCHW), replicating straight-through fp32 arithmetic ----
#pragma unroll 4
    for (int i = 0; i < 128; i++) {
        int idx2 = t + i * 256;
        int d = idx2 >> 7, ql = idx2 & 127;
        float zv = sz[d * 128 + ql];
        float cv = cb[(size_t)sidx[ql] * D_DIM + d];
        // ref: z + stopgrad(zq - z)  ->  fl(z + fl(zq - z))
        out[(size_t)b * (D_DIM * HW) + (size_t)d * HW + hw0 + ql] =
            __fadd_rn(zv, __fsub_rn(cv, zv));
    }
}

extern "C" void kernel_launch(void* const* d_in, const int* in_sizes, int n_in,
                              void* d_out, int out_size) {
    const float* z_e = (const float*)d_in[0];   // [16,256,32,32] fp32
    const float* cb  = (const float*)d_in[1];   // [8192,256] fp32
    float* out = (float*)d_out;

    static bool attr_done = false;
    const size_t smem_bytes = (size_t)(256 * 128 + 256 * 64 + 64) * sizeof(float);
    if (!attr_done) {
        cudaFuncSetAttribute(k_main, cudaFuncAttributeMaxDynamicSharedMemorySize,
                             (int)smem_bytes);
        attr_done = true;
    }

    int write_idx = (out_size >= (int)(N_Q * D_DIM + N_Q)) ? 1 : 0;

    k_transpose<<<dim3(K_CODES / 32, D_DIM / 32), dim3(32, 8)>>>(cb);
    k_c2<<<(K_CODES * 32) / 256, 256>>>(cb);
    k_z2<<<N_Q / 256, 256>>>(z_e);
    k_main<<<N_Q / QT, 256, smem_bytes>>>(z_e, cb, out, write_idx);
}